// round 10
// baseline (speedup 1.0000x reference)
#include <cuda_runtime.h>
#include <cuda_bf16.h>

// BERTLatticeEmbedding: ragged segment mean-pool.
// hidden [B,S,H] f32, word_ids [B,S] int32 (sorted per row),
// out [B,T,H] f32. B=64, S=512, H=768, T=400.
//
// R7: K1 builds lower_bound table g_start[b][0..T].
//     K2: flat warp-task = (b, word-pair, FULL row). 3 boundaries via one
//     coalesced load + shfl. Inner loop issues 12 independent LDG.128
//     (2 pieces x 6 chunks) before any FADD consumption -> deep MLP.

#define B_DIM 64
#define S_DIM 512
#define H_DIM 768
#define T_DIM 400
#define H4    (H_DIM / 4)     // 192 float4 per row
#define NC    6               // float4 chunks per lane per row (6*32*4 = 768)
#define TPB   128
#define TASKS_PER_B (T_DIM / 2)   // 200 word pairs

__device__ int g_start[B_DIM * (T_DIM + 1)];

__global__ __launch_bounds__(512) void bounds_kernel(
    const int* __restrict__ word_ids)
{
    __shared__ int s_row[S_DIM];
    const int b   = blockIdx.x;
    const int tid = threadIdx.x;

    s_row[tid] = word_ids[b * S_DIM + tid];
    __syncthreads();

    if (tid <= T_DIM) {
        int lo = 0, hi = S_DIM;
        while (lo < hi) {
            int mid = (lo + hi) >> 1;
            if (s_row[mid] < tid) lo = mid + 1; else hi = mid;
        }
        g_start[b * (T_DIM + 1) + tid] = lo;
    }
}

__device__ __forceinline__ void f4add(float4& a, const float4 v) {
    a.x += v.x; a.y += v.y; a.z += v.z; a.w += v.w;
}
__device__ __forceinline__ void f4scale(float4& a, const float s) {
    a.x *= s; a.y *= s; a.z *= s; a.w *= s;
}

__global__ __launch_bounds__(TPB) void pool_kernel(
    const float* __restrict__ hidden,
    float* __restrict__ out)
{
    const int warp = threadIdx.x >> 5;
    const int lane = threadIdx.x & 31;
    const int task = blockIdx.x * (TPB / 32) + warp;  // 0 .. B*200-1
    const int b    = task / TASKS_PER_B;
    const int wp   = task - b * TASKS_PER_B;          // word pair 0..199
    const int w0   = wp * 2;

    // Boundaries start[w0], start[w0+1], start[w0+2]: one coalesced load + shfl.
    const int* __restrict__ stp = g_start + b * (T_DIM + 1) + w0;
    const int myb = __ldg(stp + (lane < 2 ? lane : 2));
    const unsigned FULL = 0xffffffffu;
    const int s0 = __shfl_sync(FULL, myb, 0);
    const int s1 = __shfl_sync(FULL, myb, 1);
    const int s2 = __shfl_sync(FULL, myb, 2);

    const float4* __restrict__ hin =
        reinterpret_cast<const float4*>(hidden + (size_t)b * S_DIM * H_DIM) + lane;

    const float4 Z = make_float4(0.f, 0.f, 0.f, 0.f);
    float4 A[NC], Bc[NC];
    #pragma unroll
    for (int c = 0; c < NC; ++c) { A[c] = Z; Bc[c] = Z; }

    // Combined contiguous piece range [s0, s2); warp-uniform predicates.
    for (int s = s0; s < s2; s += 2) {
        const float4* q = hin + (size_t)s * H4;
        const bool has1 = (s + 1 < s2);

        float4 v[NC], u[NC];
        #pragma unroll
        for (int c = 0; c < NC; ++c) v[c] = __ldcs(q + c * 32);
        if (has1) {
            #pragma unroll
            for (int c = 0; c < NC; ++c) u[c] = __ldcs(q + H4 + c * 32);
        }

        if (s < s1) {
            #pragma unroll
            for (int c = 0; c < NC; ++c) f4add(A[c], v[c]);
        } else {
            #pragma unroll
            for (int c = 0; c < NC; ++c) f4add(Bc[c], v[c]);
        }
        if (has1) {
            if (s + 1 < s1) {
                #pragma unroll
                for (int c = 0; c < NC; ++c) f4add(A[c], u[c]);
            } else {
                #pragma unroll
                for (int c = 0; c < NC; ++c) f4add(Bc[c], u[c]);
            }
        }
    }

    const int c0 = s1 - s0;
    const int c1 = s2 - s1;
    const float invA = 1.0f / (float)(c0 > 0 ? c0 : 1);
    const float invB = 1.0f / (float)(c1 > 0 ? c1 : 1);
    #pragma unroll
    for (int c = 0; c < NC; ++c) { f4scale(A[c], invA); f4scale(Bc[c], invB); }

    float4* __restrict__ opA =
        reinterpret_cast<float4*>(out + ((size_t)b * T_DIM + w0) * H_DIM) + lane;
    float4* __restrict__ opB = opA + H4;
    #pragma unroll
    for (int c = 0; c < NC; ++c) {
        __stcs(opA + c * 32, A[c]);
        __stcs(opB + c * 32, Bc[c]);
    }
}

extern "C" void kernel_launch(void* const* d_in, const int* in_sizes, int n_in,
                              void* d_out, int out_size)
{
    const float* hidden   = (const float*)d_in[0];
    const int*   word_ids = (const int*)d_in[1];
    float* out = (float*)d_out;

    bounds_kernel<<<B_DIM, 512>>>(word_ids);

    const int total_tasks = B_DIM * TASKS_PER_B;       // 12800 warp-tasks
    pool_kernel<<<total_tasks / (TPB / 32), TPB>>>(hidden, out);
}